// round 1
// baseline (speedup 1.0000x reference)
#include <cuda_runtime.h>

#define VOCAB 81616
#define DIM 32
#define BATCH 4096

typedef unsigned long long u64;

// ---------------- pass 1 config ----------------
#define BM 128
#define BK 32
#define NSPLIT 9
#define NTILES ((VOCAB + BK - 1) / BK)        // 2551
#define TPS ((NTILES + NSPLIT - 1) / NSPLIT)  // 284
#define ROWBLOCKS (BATCH / BM)                // 32

// ---------------- pass 2 config ----------------
#define P2_ROWS 64
#define P2_THREADS 256
#define P2_JSPAN (P2_THREADS * 2)             // 512 vocab cols per block

// Scratch (no cudaMalloc allowed — device globals)
__device__ float g_partial[NSPLIT * BATCH * DIM];  // 4.7 MB
__device__ float g_h[BATCH * DIM];                 // 512 KB

// ---------------- f32x2 helpers ----------------
__device__ __forceinline__ u64 fma2(u64 a, u64 b, u64 c) {
    u64 d;
    asm("fma.rn.f32x2 %0, %1, %2, %3;" : "=l"(d) : "l"(a), "l"(b), "l"(c));
    return d;
}

__device__ __forceinline__ float lanesum(u64 v) {
    float lo, hi;
    asm("mov.b64 {%0, %1}, %2;" : "=f"(lo), "=f"(hi) : "l"(v));
    return lo + hi;
}

__device__ __forceinline__ float sigmoidf(float x) {
    return __fdividef(1.0f, 1.0f + __expf(-x));
}

// =====================================================================
// Pass 1: partial[s] = x[rows] @ w  over this split's K-chunk
// Block: 256 threads, tile [BM=128 rows x BK=32 k].
// Thread (rowg = t>>3 in 0..31, colg = t&7): rows rowg+32q (q=0..3),
// cols 4*colg..+3. Accumulators are f32x2 paired over k (even/odd k in
// the two lanes) so both x and wT smem loads are natural LDS.64.
// =====================================================================
__global__ __launch_bounds__(256) void pass1_kernel(const float* __restrict__ X,
                                                    const float* __restrict__ W) {
    __shared__ float xs[BM * 36];   // row-major, stride 36 (16B-aligned rows, conflict-free LDS.64)
    __shared__ float ws[DIM * 34];  // wT tile: [j][kk], stride 34

    const int t = threadIdx.x;
    const int rb = blockIdx.x;
    const int s  = blockIdx.y;
    const int row0 = rb * BM;
    const int rowg = t >> 3;
    const int colg = t & 7;

    u64 acc[16];
#pragma unroll
    for (int i = 0; i < 16; ++i) acc[i] = 0ULL;  // (0.0f, 0.0f)

    const int tile0 = s * TPS;
    const int tile1 = (tile0 + TPS < NTILES) ? (tile0 + TPS) : NTILES;

    for (int tile = tile0; tile < tile1; ++tile) {
        const int k0 = tile * BK;

        // ---- load x tile: 128 rows x 32 k = 1024 float4, 4 per thread ----
#pragma unroll
        for (int i = 0; i < 4; ++i) {
            int e   = i * 256 + t;
            int row = e >> 3;
            int kq  = e & 7;
            int gk  = k0 + kq * 4;
            float4 v = make_float4(0.f, 0.f, 0.f, 0.f);
            if (gk < VOCAB)  // VOCAB % 4 == 0, gk % 4 == 0 -> full float4 valid
                v = *reinterpret_cast<const float4*>(X + (size_t)(row0 + row) * VOCAB + gk);
            *reinterpret_cast<float4*>(&xs[row * 36 + kq * 4]) = v;
        }
        // ---- load w tile, transposed on the fly: ws[j][kk] = W[k0+kk][j] ----
#pragma unroll
        for (int i = 0; i < 4; ++i) {
            int e  = i * 256 + t;
            int kk = e >> 5;
            int j  = e & 31;
            int gk = k0 + kk;
            ws[j * 34 + kk] = (gk < VOCAB) ? W[(size_t)gk * DIM + j] : 0.f;
        }
        __syncthreads();

#pragma unroll 4
        for (int p = 0; p < 16; ++p) {  // k-pair index
            u64 x2[4], w2[4];
#pragma unroll
            for (int q = 0; q < 4; ++q)
                x2[q] = *reinterpret_cast<const u64*>(&xs[(rowg + 32 * q) * 36 + 2 * p]);
#pragma unroll
            for (int c = 0; c < 4; ++c)
                w2[c] = *reinterpret_cast<const u64*>(&ws[(colg * 4 + c) * 34 + 2 * p]);
#pragma unroll
            for (int q = 0; q < 4; ++q)
#pragma unroll
                for (int c = 0; c < 4; ++c)
                    acc[q * 4 + c] = fma2(x2[q], w2[c], acc[q * 4 + c]);
        }
        __syncthreads();
    }

    // ---- epilogue: reduce f32x2 lanes, write partial ----
#pragma unroll
    for (int q = 0; q < 4; ++q) {
        int row = row0 + rowg + 32 * q;
        float4 o;
        o.x = lanesum(acc[q * 4 + 0]);
        o.y = lanesum(acc[q * 4 + 1]);
        o.z = lanesum(acc[q * 4 + 2]);
        o.w = lanesum(acc[q * 4 + 3]);
        *reinterpret_cast<float4*>(&g_partial[((size_t)s * BATCH + row) * DIM + colg * 4]) = o;
    }
}

// =====================================================================
// Reduce partials + bias + sigmoid -> g_h
// =====================================================================
__global__ void reduce_act_kernel(const float* __restrict__ b) {
    int idx = blockIdx.x * blockDim.x + threadIdx.x;
    if (idx >= BATCH * DIM) return;
    float sum = b[idx & (DIM - 1)];
#pragma unroll
    for (int s = 0; s < NSPLIT; ++s)
        sum += g_partial[(size_t)s * BATCH * DIM + idx];
    g_h[idx] = sigmoidf(sum);
}

// =====================================================================
// Pass 2: y = sigmoid(h @ w^T)
// Block: 256 threads, [64 rows x 512 vocab cols]. Thread owns 2 adjacent
// vocab cols with both w rows register-resident as f32x2 k-pairs; loops
// 64 rows pulling h via broadcast LDS.64.
// =====================================================================
__global__ __launch_bounds__(256) void pass2_kernel(const float* __restrict__ W,
                                                    float* __restrict__ Y) {
    __shared__ float hs[P2_ROWS * DIM];  // 8 KB

    const int t  = threadIdx.x;
    const int jb = blockIdx.x * P2_JSPAN;
    const int ib = blockIdx.y * P2_ROWS;

    // load h tile (64 x 32 floats = 512 float4, 2 per thread)
#pragma unroll
    for (int i = 0; i < 2; ++i) {
        int e   = i * 256 + t;
        int row = e >> 3;
        int q   = e & 7;
        *reinterpret_cast<float4*>(&hs[row * DIM + q * 4]) =
            *reinterpret_cast<const float4*>(&g_h[(size_t)(ib + row) * DIM + q * 4]);
    }

    const int j = jb + 2 * t;                 // even; VOCAB even -> j valid => j+1 valid
    const bool valid = (j < VOCAB);

    u64 wa[16], wb[16];
    if (valid) {
        const u64* pa = reinterpret_cast<const u64*>(W + (size_t)j * DIM);
        const u64* pb = pa + 16;              // row j+1
#pragma unroll
        for (int p = 0; p < 16; ++p) { wa[p] = pa[p]; wb[p] = pb[p]; }
    }
    __syncthreads();
    if (!valid) return;

    for (int r = 0; r < P2_ROWS; ++r) {
        u64 aa = 0ULL, ab = 0ULL;
#pragma unroll
        for (int p = 0; p < 16; ++p) {
            u64 h2 = *reinterpret_cast<const u64*>(&hs[r * DIM + 2 * p]);
            aa = fma2(h2, wa[p], aa);
            ab = fma2(h2, wb[p], ab);
        }
        float2 o;
        o.x = sigmoidf(lanesum(aa));
        o.y = sigmoidf(lanesum(ab));
        *reinterpret_cast<float2*>(&Y[(size_t)(ib + r) * VOCAB + j]) = o;
    }
}

// =====================================================================
extern "C" void kernel_launch(void* const* d_in, const int* in_sizes, int n_in,
                              void* d_out, int out_size) {
    const float* x = (const float*)d_in[0];  // [4096, 81616]
    const float* w = (const float*)d_in[1];  // [81616, 32]
    const float* b = (const float*)d_in[2];  // [32]
    float* y = (float*)d_out;                // [4096, 81616]

    dim3 g1(ROWBLOCKS, NSPLIT);
    pass1_kernel<<<g1, 256>>>(x, w);

    reduce_act_kernel<<<(BATCH * DIM + 255) / 256, 256>>>(b);

    dim3 g2((VOCAB + P2_JSPAN - 1) / P2_JSPAN, BATCH / P2_ROWS);
    pass2_kernel<<<g2, P2_THREADS>>>(w, y);
}

// round 4
// speedup vs baseline: 1.1862x; 1.1862x over previous
#include <cuda_runtime.h>

#define VOCAB 81616
#define DIM 32
#define BATCH 4096

typedef unsigned long long u64;

// ---------------- pass 1 config ----------------
#define BM 256
#define BK 32
#define NSPLIT 20
#define NTILES ((VOCAB + BK - 1) / BK)        // 2551
#define TPS ((NTILES + NSPLIT - 1) / NSPLIT)  // 128
#define ROWBLOCKS (BATCH / BM)                // 16

#define WS_STRIDE 34   // even: u64 reads land on 8B; reads are warp-uniform broadcasts

// ---------------- pass 2 config ----------------
#define P2_ROWS 64
#define P2_THREADS 256
#define P2_JSPAN (P2_THREADS * 2)             // 512 vocab cols per block

// Scratch (no cudaMalloc allowed — device globals)
__device__ __align__(16) float g_partial[NSPLIT * BATCH * DIM];  // 10.5 MB
__device__ __align__(16) float g_h[BATCH * DIM];                 // 512 KB

// ---------------- f32x2 helpers ----------------
__device__ __forceinline__ u64 fma2(u64 a, u64 b, u64 c) {
    u64 d;
    asm("fma.rn.f32x2 %0, %1, %2, %3;" : "=l"(d) : "l"(a), "l"(b), "l"(c));
    return d;
}

__device__ __forceinline__ u64 pack2(float lo, float hi) {
    u64 v;
    asm("mov.b64 %0, {%1, %2};" : "=l"(v) : "f"(lo), "f"(hi));
    return v;
}

__device__ __forceinline__ float lanesum(u64 v) {
    float lo, hi;
    asm("mov.b64 {%0, %1}, %2;" : "=f"(lo), "=f"(hi) : "l"(v));
    return lo + hi;
}

__device__ __forceinline__ float sigmoidf(float x) {
    return __fdividef(1.0f, 1.0f + __expf(-x));
}

// =====================================================================
// Pass 1: partial[s] = x[rows] @ w  over this split's K-chunk
// Block: 128 threads = 4 warps, tile [BM=256 rows x BK=32 k].
// Warp wid owns output cols 8*wid..+7 (warp-uniform -> w smem loads are
// broadcasts). Lane owns rows lane+32q (q=0..7).
// x tile lives in shared as u64 k-pairs, XOR-swizzled within each row:
// logical pair p of row r is stored at  xs[r*16 + (p ^ (r & 15))].
//   - u64 type => 8B alignment by construction (no reinterpret hazards)
//   - reads: bank-pair = (p ^ lane&15) -> distinct per half-warp lane
//   - stores: 2 STS.64 per float4, indices (2kq)^r15 / (2kq+1)^r15
// Per k-pair per warp: 8 x-LDS.64 + 8 broadcast w-LDS.64 + 64 FFMA2.
// =====================================================================
__global__ __launch_bounds__(128, 2) void pass1_kernel(const float* __restrict__ X,
                                                       const float* __restrict__ W) {
    __shared__ u64   xs[BM * 16];          // 32 KB, swizzled
    __shared__ float ws[DIM * WS_STRIDE];  // 4.25 KB  (wT tile: [j][kk])

    const int t    = threadIdx.x;
    const int lane = t & 31;
    const int wid  = t >> 5;               // warp-uniform output column group (8 cols)
    const int row0 = blockIdx.x * BM;
    const int s    = blockIdx.y;
    const int sw   = lane & 15;            // read-side swizzle key (rows differ by 32)

    u64 acc[64];
#pragma unroll
    for (int i = 0; i < 64; ++i) acc[i] = 0ULL;

    const int tile0 = s * TPS;
    const int tile1 = (tile0 + TPS < NTILES) ? (tile0 + TPS) : NTILES;

    for (int tile = tile0; tile < tile1; ++tile) {
        const int k0 = tile * BK;

        // ---- x tile: 256 rows x 32 k = 2048 float4, 16 per thread ----
#pragma unroll
        for (int i = 0; i < 16; ++i) {
            int e   = i * 128 + t;
            int row = e >> 3;
            int kq  = e & 7;
            int gk  = k0 + kq * 4;
            float4 v = make_float4(0.f, 0.f, 0.f, 0.f);
            if (gk < VOCAB)   // VOCAB%4==0, gk%4==0 -> whole float4 in-bounds
                v = *reinterpret_cast<const float4*>(X + (size_t)(row0 + row) * VOCAB + gk);
            int r15 = row & 15;
            xs[row * 16 + ((2 * kq)     ^ r15)] = pack2(v.x, v.y);
            xs[row * 16 + ((2 * kq + 1) ^ r15)] = pack2(v.z, v.w);
        }
        // ---- w tile, transposed on the fly: ws[j][kk] = W[k0+kk][j] ----
        {
            int kk = t >> 5;   // 0..3
            int j  = t & 31;
#pragma unroll
            for (int i = 0; i < 8; ++i) {
                int gk = k0 + kk + i * 4;
                ws[j * WS_STRIDE + kk + i * 4] = (gk < VOCAB) ? W[(size_t)gk * DIM + j] : 0.f;
            }
        }
        __syncthreads();

#pragma unroll 4
        for (int p = 0; p < 16; ++p) {  // k-pair index
            u64 x2[8], w2[8];
#pragma unroll
            for (int q = 0; q < 8; ++q)
                x2[q] = xs[(lane + 32 * q) * 16 + (p ^ sw)];
#pragma unroll
            for (int c = 0; c < 8; ++c)
                w2[c] = *reinterpret_cast<const u64*>(&ws[(wid * 8 + c) * WS_STRIDE + 2 * p]);
#pragma unroll
            for (int q = 0; q < 8; ++q)
#pragma unroll
                for (int c = 0; c < 8; ++c)
                    acc[q * 8 + c] = fma2(x2[q], w2[c], acc[q * 8 + c]);
        }
        __syncthreads();
    }

    // ---- epilogue: reduce f32x2 lanes, write partial ----
#pragma unroll
    for (int q = 0; q < 8; ++q) {
        int row = row0 + lane + 32 * q;
        float* dst = &g_partial[((size_t)s * BATCH + row) * DIM + wid * 8];
        float4 o0, o1;
        o0.x = lanesum(acc[q * 8 + 0]);
        o0.y = lanesum(acc[q * 8 + 1]);
        o0.z = lanesum(acc[q * 8 + 2]);
        o0.w = lanesum(acc[q * 8 + 3]);
        o1.x = lanesum(acc[q * 8 + 4]);
        o1.y = lanesum(acc[q * 8 + 5]);
        o1.z = lanesum(acc[q * 8 + 6]);
        o1.w = lanesum(acc[q * 8 + 7]);
        *reinterpret_cast<float4*>(dst)     = o0;   // wid*8*4B -> 32B-aligned
        *reinterpret_cast<float4*>(dst + 4) = o1;
    }
}

// =====================================================================
// Reduce partials + bias + sigmoid -> g_h
// =====================================================================
__global__ void reduce_act_kernel(const float* __restrict__ b) {
    int idx = blockIdx.x * blockDim.x + threadIdx.x;
    if (idx >= BATCH * DIM) return;
    float sum = b[idx & (DIM - 1)];
#pragma unroll
    for (int s = 0; s < NSPLIT; ++s)
        sum += g_partial[(size_t)s * BATCH * DIM + idx];
    g_h[idx] = sigmoidf(sum);
}

// =====================================================================
// Pass 2: y = sigmoid(h @ w^T)   [round-1-proven structure, unchanged]
// Block: 256 threads, [64 rows x 512 vocab cols]. Thread owns 2 adjacent
// vocab cols with both w rows register-resident as f32x2 k-pairs; loops
// 64 rows pulling h via broadcast LDS.64 (single-address, conflict-free).
// =====================================================================
__global__ __launch_bounds__(256) void pass2_kernel(const float* __restrict__ W,
                                                    float* __restrict__ Y) {
    __shared__ float hs[P2_ROWS * DIM];  // 8 KB

    const int t  = threadIdx.x;
    const int jb = blockIdx.x * P2_JSPAN;
    const int ib = blockIdx.y * P2_ROWS;

    // load h tile (64 x 32 floats = 512 float4, 2 per thread); DIM=32 -> 16B-aligned
#pragma unroll
    for (int i = 0; i < 2; ++i) {
        int e   = i * 256 + t;
        int row = e >> 3;
        int q   = e & 7;
        *reinterpret_cast<float4*>(&hs[row * DIM + q * 4]) =
            *reinterpret_cast<const float4*>(&g_h[(size_t)(ib + row) * DIM + q * 4]);
    }

    const int j = jb + 2 * t;                 // even; VOCAB even -> j valid => j+1 valid
    const bool valid = (j < VOCAB);

    u64 wa[16], wb[16];
    if (valid) {
        const u64* pa = reinterpret_cast<const u64*>(W + (size_t)j * DIM);
        const u64* pb = pa + 16;              // row j+1
#pragma unroll
        for (int p = 0; p < 16; ++p) { wa[p] = pa[p]; wb[p] = pb[p]; }
    }
    __syncthreads();
    if (!valid) return;

#pragma unroll 2
    for (int r = 0; r < P2_ROWS; ++r) {
        u64 aa = 0ULL, ab = 0ULL;
#pragma unroll
        for (int p = 0; p < 16; ++p) {
            u64 h2 = *reinterpret_cast<const u64*>(&hs[r * DIM + 2 * p]);
            aa = fma2(h2, wa[p], aa);
            ab = fma2(h2, wb[p], ab);
        }
        float2 o;
        o.x = sigmoidf(lanesum(aa));
        o.y = sigmoidf(lanesum(ab));
        *reinterpret_cast<float2*>(&Y[(size_t)(ib + r) * VOCAB + j]) = o;
    }
}

// =====================================================================
extern "C" void kernel_launch(void* const* d_in, const int* in_sizes, int n_in,
                              void* d_out, int out_size) {
    const float* x = (const float*)d_in[0];  // [4096, 81616]
    const float* w = (const float*)d_in[1];  // [81616, 32]
    const float* b = (const float*)d_in[2];  // [32]
    float* y = (float*)d_out;                // [4096, 81616]

    dim3 g1(ROWBLOCKS, NSPLIT);
    pass1_kernel<<<g1, 128>>>(x, w);

    reduce_act_kernel<<<(BATCH * DIM + 255) / 256, 256>>>(b);

    dim3 g2((VOCAB + P2_JSPAN - 1) / P2_JSPAN, BATCH / P2_ROWS);
    pass2_kernel<<<g2, P2_THREADS>>>(w, y);
}

// round 5
// speedup vs baseline: 1.7908x; 1.5097x over previous
#include <cuda_runtime.h>

#define VOCAB 81616
#define DIM 32
#define BATCH 4096

typedef unsigned long long u64;

// ---------------- pass 1 config ----------------
#define BM 256
#define BK 32
#define NSPLIT 18
#define NTILES ((VOCAB + BK - 1) / BK)        // 2551
#define TPS ((NTILES + NSPLIT - 1) / NSPLIT)  // 142
#define ROWBLOCKS (BATCH / BM)                // 16
#define WS_STRIDE 34

#define P1_XS_BYTES (BM * 16 * 8)             // 32768 per buffer
#define P1_WS_BYTES (DIM * WS_STRIDE * 4)     // 4352 per buffer
#define P1_SMEM (2 * P1_XS_BYTES + 2 * P1_WS_BYTES)  // 74240

// ---------------- pass 2 config ----------------
#define P2_ROWS 64
#define P2_CHUNKS 8
#define P2_THREADS 256
#define P2_JSPAN (P2_THREADS * 2)             // 512 vocab cols per block

// Scratch (no cudaMalloc allowed — device globals)
__device__ __align__(16) float g_partial[NSPLIT * BATCH * DIM];  // 9.4 MB
__device__ __align__(16) float g_h[BATCH * DIM];                 // 512 KB

// ---------------- helpers ----------------
__device__ __forceinline__ u64 fma2(u64 a, u64 b, u64 c) {
    u64 d;
    asm("fma.rn.f32x2 %0, %1, %2, %3;" : "=l"(d) : "l"(a), "l"(b), "l"(c));
    return d;
}

__device__ __forceinline__ float lanesum(u64 v) {
    float lo, hi;
    asm("mov.b64 {%0, %1}, %2;" : "=f"(lo), "=f"(hi) : "l"(v));
    return lo + hi;
}

// sigmoid(x) = 0.5*tanh(0.5x) + 0.5  (MUFU.TANH, ~1e-5 abs err, threshold 1e-3)
__device__ __forceinline__ float sigt(float x) {
    float t;
    asm("tanh.approx.f32 %0, %1;" : "=f"(t) : "f"(x * 0.5f));
    return fmaf(0.5f, t, 0.5f);
}

__device__ __forceinline__ unsigned smem_u32(const void* p) {
    unsigned a;
    asm("{ .reg .u64 t; cvta.to.shared.u64 t, %1; cvt.u32.u64 %0, t; }" : "=r"(a) : "l"(p));
    return a;
}

__device__ __forceinline__ void cp8(unsigned dst, const void* src, unsigned sz) {
    asm volatile("cp.async.ca.shared.global [%0], [%1], 8, %2;" :: "r"(dst), "l"(src), "r"(sz));
}
__device__ __forceinline__ void cp4(unsigned dst, const void* src, unsigned sz) {
    asm volatile("cp.async.ca.shared.global [%0], [%1], 4, %2;" :: "r"(dst), "l"(src), "r"(sz));
}
__device__ __forceinline__ void cp16(unsigned dst, const void* src) {
    asm volatile("cp.async.ca.shared.global [%0], [%1], 16;" :: "r"(dst), "l"(src));
}
#define CP_COMMIT() asm volatile("cp.async.commit_group;")
#define CP_WAIT1()  asm volatile("cp.async.wait_group 1;")

// =====================================================================
// Pass 1: partial[s] = x[rows] @ w over this split's K-chunk.
// 128 threads = 4 warps; warp wid owns cols 8*wid..+7 (w loads broadcast),
// lane owns rows lane+32q (q=0..7). x tile = u64 k-pairs XOR-swizzled
// (slot = p ^ (row&15)) -> conflict-free reads AND cp.async 8B writes.
// Double-buffered cp.async pipeline; zero staging registers.
// =====================================================================
__device__ __forceinline__ void p1_load(unsigned sb, int buf, int tile,
                                        const float* __restrict__ X,
                                        const float* __restrict__ W,
                                        int row0, int t) {
    const int k0 = tile * BK;
    const unsigned xbase = sb + (unsigned)buf * P1_XS_BYTES;
    const unsigned wbase = sb + 2u * P1_XS_BYTES + (unsigned)buf * P1_WS_BYTES;

    // x: 256 rows x 16 u64 = 4096 u64, 32 per thread (8B cp.async, coalesced)
    const int u  = t & 15;       // u64 index within row
    const int r0 = t >> 4;       // 0..7
    const int gk = k0 + 2 * u;
    const unsigned szx = (gk < VOCAB) ? 8u : 0u;   // VOCAB even -> u64 all-or-none
    const float* srcx = (gk < VOCAB) ? (X + (size_t)(row0 + r0) * VOCAB + gk) : X;
#pragma unroll
    for (int i = 0; i < 32; ++i) {
        int row = i * 8 + r0;
        unsigned slot = (unsigned)(u ^ (row & 15));
        cp8(xbase + (unsigned)(row * 16 + slot) * 8u, srcx, szx);
        srcx += (size_t)8 * VOCAB;
    }

    // w tile transposed: ws[j][kk] = W[k0+kk][j], 1024 floats, 8 per thread
    const int j  = t & 31;
    const int kb = t >> 5;       // warp id 0..3
#pragma unroll
    for (int i = 0; i < 8; ++i) {
        int kk = kb + i * 4;
        int g  = k0 + kk;
        unsigned sz = (g < VOCAB) ? 4u : 0u;
        const float* src = (g < VOCAB) ? (W + (size_t)g * DIM + j) : W;
        cp4(wbase + (unsigned)(j * WS_STRIDE + kk) * 4u, src, sz);
    }
}

__global__ __launch_bounds__(128, 2) void pass1_kernel(const float* __restrict__ X,
                                                       const float* __restrict__ W) {
    extern __shared__ char smem[];
    const unsigned sb = smem_u32(smem);

    const int t    = threadIdx.x;
    const int lane = t & 31;
    const int wid  = t >> 5;
    const int row0 = blockIdx.x * BM;
    const int s    = blockIdx.y;
    const int sw   = lane & 15;

    u64 acc[64];
#pragma unroll
    for (int i = 0; i < 64; ++i) acc[i] = 0ULL;

    const int tile0 = s * TPS;
    const int tile1 = (tile0 + TPS < NTILES) ? (tile0 + TPS) : NTILES;
    const int nt    = tile1 - tile0;

    p1_load(sb, 0, tile0, X, W, row0, t);
    CP_COMMIT();

    for (int i = 0; i < nt; ++i) {
        if (i + 1 < nt) p1_load(sb, (i + 1) & 1, tile0 + i + 1, X, W, row0, t);
        CP_COMMIT();
        CP_WAIT1();
        __syncthreads();

        const int buf = i & 1;
        const u64*   xp = reinterpret_cast<const u64*>(smem + buf * P1_XS_BYTES);
        const float* wp = reinterpret_cast<const float*>(smem + 2 * P1_XS_BYTES + buf * P1_WS_BYTES);

#pragma unroll 4
        for (int p = 0; p < 16; ++p) {
            u64 x2[8], w2[8];
#pragma unroll
            for (int q = 0; q < 8; ++q)
                x2[q] = xp[(lane + 32 * q) * 16 + (p ^ sw)];
#pragma unroll
            for (int c = 0; c < 8; ++c)
                w2[c] = *reinterpret_cast<const u64*>(&wp[(wid * 8 + c) * WS_STRIDE + 2 * p]);
#pragma unroll
            for (int q = 0; q < 8; ++q)
#pragma unroll
                for (int c = 0; c < 8; ++c)
                    acc[q * 8 + c] = fma2(x2[q], w2[c], acc[q * 8 + c]);
        }
        __syncthreads();
    }

    // epilogue: reduce f32x2 lanes, write partial
#pragma unroll
    for (int q = 0; q < 8; ++q) {
        int row = row0 + lane + 32 * q;
        float* dst = &g_partial[((size_t)s * BATCH + row) * DIM + wid * 8];
        float4 o0, o1;
        o0.x = lanesum(acc[q * 8 + 0]);
        o0.y = lanesum(acc[q * 8 + 1]);
        o0.z = lanesum(acc[q * 8 + 2]);
        o0.w = lanesum(acc[q * 8 + 3]);
        o1.x = lanesum(acc[q * 8 + 4]);
        o1.y = lanesum(acc[q * 8 + 5]);
        o1.z = lanesum(acc[q * 8 + 6]);
        o1.w = lanesum(acc[q * 8 + 7]);
        *reinterpret_cast<float4*>(dst)     = o0;
        *reinterpret_cast<float4*>(dst + 4) = o1;
    }
}

// =====================================================================
// Reduce partials + bias + sigmoid -> g_h
// =====================================================================
__global__ void reduce_act_kernel(const float* __restrict__ b) {
    int idx = blockIdx.x * blockDim.x + threadIdx.x;
    if (idx >= BATCH * DIM) return;
    float sum = b[idx & (DIM - 1)];
#pragma unroll
    for (int s = 0; s < NSPLIT; ++s)
        sum += g_partial[(size_t)s * BATCH * DIM + idx];
    g_h[idx] = sigt(sum);
}

// =====================================================================
// Pass 2: y = sigmoid(h @ w^T)
// Grid (160 j-blocks, 8 ib-groups). CTA loops 8 chunks of 64 rows:
// w registers loaded ONCE per 512 rows; h tiles double-buffered via
// 16B cp.async. Thread owns 2 adjacent vocab cols (w rows in regs as
// f32x2 k-pairs); h read via broadcast LDS.64.
// =====================================================================
__device__ __forceinline__ void p2_load(unsigned hbase, int buf, int ib, int t) {
    const unsigned dst0 = hbase + (unsigned)buf * (P2_ROWS * DIM * 4);
#pragma unroll
    for (int i = 0; i < 2; ++i) {
        int e   = i * P2_THREADS + t;
        int row = e >> 3;
        int q   = e & 7;
        cp16(dst0 + (unsigned)(row * DIM + q * 4) * 4u,
             &g_h[(size_t)(ib + row) * DIM + q * 4]);
    }
}

__global__ __launch_bounds__(P2_THREADS, 2) void pass2_kernel(const float* __restrict__ W,
                                                              float* __restrict__ Y) {
    __shared__ float hs[2][P2_ROWS * DIM];  // 16 KB
    const unsigned hbase = smem_u32(&hs[0][0]);

    const int t   = threadIdx.x;
    const int jb  = blockIdx.x * P2_JSPAN;
    const int ib0 = blockIdx.y * (P2_ROWS * P2_CHUNKS);

    p2_load(hbase, 0, ib0, t);
    CP_COMMIT();

    const int j = jb + 2 * t;                 // even; j valid => j+1 valid
    const bool valid = (j < VOCAB);

    u64 wa[16], wb[16];
    if (valid) {
        const u64* pa = reinterpret_cast<const u64*>(W + (size_t)j * DIM);
        const u64* pb = pa + 16;              // row j+1
#pragma unroll
        for (int p = 0; p < 16; ++p) { wa[p] = pa[p]; wb[p] = pb[p]; }
    }

    for (int c = 0; c < P2_CHUNKS; ++c) {
        if (c + 1 < P2_CHUNKS) p2_load(hbase, (c + 1) & 1, ib0 + (c + 1) * P2_ROWS, t);
        CP_COMMIT();
        CP_WAIT1();
        __syncthreads();

        if (valid) {
            const float* hb = &hs[c & 1][0];
            const int ib = ib0 + c * P2_ROWS;
#pragma unroll 2
            for (int r = 0; r < P2_ROWS; ++r) {
                u64 aa = 0ULL, ab = 0ULL;
#pragma unroll
                for (int p = 0; p < 16; ++p) {
                    u64 h2 = *reinterpret_cast<const u64*>(&hb[r * DIM + 2 * p]);
                    aa = fma2(h2, wa[p], aa);
                    ab = fma2(h2, wb[p], ab);
                }
                float2 o;
                o.x = sigt(lanesum(aa));
                o.y = sigt(lanesum(ab));
                *reinterpret_cast<float2*>(&Y[(size_t)(ib + r) * VOCAB + j]) = o;
            }
        }
        __syncthreads();
    }
}

// =====================================================================
extern "C" void kernel_launch(void* const* d_in, const int* in_sizes, int n_in,
                              void* d_out, int out_size) {
    const float* x = (const float*)d_in[0];  // [4096, 81616]
    const float* w = (const float*)d_in[1];  // [81616, 32]
    const float* b = (const float*)d_in[2];  // [32]
    float* y = (float*)d_out;                // [4096, 81616]

    cudaFuncSetAttribute(pass1_kernel, cudaFuncAttributeMaxDynamicSharedMemorySize, P1_SMEM);

    dim3 g1(ROWBLOCKS, NSPLIT);
    pass1_kernel<<<g1, 128, P1_SMEM>>>(x, w);

    reduce_act_kernel<<<(BATCH * DIM + 255) / 256, 256>>>(b);

    dim3 g2((VOCAB + P2_JSPAN - 1) / P2_JSPAN, BATCH / (P2_ROWS * P2_CHUNKS));
    pass2_kernel<<<g2, P2_THREADS>>>(w, y);
}

// round 6
// speedup vs baseline: 2.2954x; 1.2818x over previous
#include <cuda_runtime.h>
#include <cstdint>

#define VOCAB 81616
#define DIM 32
#define BATCH 4096

typedef unsigned long long u64;

// ---------------- pass 1 config ----------------
#define BM 256
#define BK 32
#define NSPLIT 18
#define NTILES ((VOCAB + BK - 1) / BK)        // 2551
#define TPS ((NTILES + NSPLIT - 1) / NSPLIT)  // 142
#define ROWBLOCKS (BATCH / BM)                // 16
#define P1_THREADS 256

#define XS_STRIDE 36                          // 144B rows: 16B-aligned, bank=4r+c
#define P1_XS_BYTES (BM * XS_STRIDE * 4)      // 36864
#define P1_WS_BYTES (BK * XS_STRIDE * 4)      // 4608
#define P1_BUF (P1_XS_BYTES + P1_WS_BYTES)    // 41472
#define P1_SMEM (2 * P1_BUF)                  // 82944

// ---------------- pass 2 config ----------------
#define P2_ROWS 64
#define P2_CHUNKS 8
#define P2_THREADS 256
#define P2_JSPAN (P2_THREADS * 2)             // 512 vocab cols per block

// Scratch (no cudaMalloc allowed — device globals)
__device__ __align__(16) float g_partial[NSPLIT * BATCH * DIM];  // 9.4 MB
__device__ __align__(16) float g_h[BATCH * DIM];                 // 512 KB

// ---------------- helpers ----------------
__device__ __forceinline__ u64 fma2(u64 a, u64 b, u64 c) {
    u64 d;
    asm("fma.rn.f32x2 %0, %1, %2, %3;" : "=l"(d) : "l"(a), "l"(b), "l"(c));
    return d;
}

__device__ __forceinline__ float lanesum(u64 v) {
    float lo, hi;
    asm("mov.b64 {%0, %1}, %2;" : "=f"(lo), "=f"(hi) : "l"(v));
    return lo + hi;
}

// sigmoid(x) = 0.5*tanh(0.5x) + 0.5
__device__ __forceinline__ float sigt(float x) {
    float t;
    asm("tanh.approx.f32 %0, %1;" : "=f"(t) : "f"(x * 0.5f));
    return fmaf(0.5f, t, 0.5f);
}

__device__ __forceinline__ unsigned smem_u32(const void* p) {
    unsigned a;
    asm("{ .reg .u64 t; cvta.to.shared.u64 t, %1; cvt.u32.u64 %0, t; }" : "=r"(a) : "l"(p));
    return a;
}

__device__ __forceinline__ void cp8(unsigned dst, const void* src, unsigned sz) {
    asm volatile("cp.async.ca.shared.global [%0], [%1], 8, %2;" :: "r"(dst), "l"(src), "r"(sz));
}
__device__ __forceinline__ void cp4(unsigned dst, const void* src, unsigned sz) {
    asm volatile("cp.async.ca.shared.global [%0], [%1], 4, %2;" :: "r"(dst), "l"(src), "r"(sz));
}
__device__ __forceinline__ void cp16(unsigned dst, const void* src) {
    asm volatile("cp.async.ca.shared.global [%0], [%1], 16;" :: "r"(dst), "l"(src));
}
#define CP_COMMIT() asm volatile("cp.async.commit_group;")
#define CP_WAIT1()  asm volatile("cp.async.wait_group 1;")

// round-to-nearest tf32 (unbiased; raw truncation would bias the 81616-term sums)
__device__ __forceinline__ uint32_t to_tf32(float f) {
    uint32_t r;
    asm("cvt.rna.tf32.f32 %0, %1;" : "=r"(r) : "f"(f));
    return r;
}

__device__ __forceinline__ void mma_tf32(float* d, const uint32_t* a, const uint32_t* b) {
    asm("mma.sync.aligned.m16n8k8.row.col.f32.tf32.tf32.f32 "
        "{%0,%1,%2,%3}, {%4,%5,%6,%7}, {%8,%9}, {%0,%1,%2,%3};"
        : "+f"(d[0]), "+f"(d[1]), "+f"(d[2]), "+f"(d[3])
        : "r"(a[0]), "r"(a[1]), "r"(a[2]), "r"(a[3]), "r"(b[0]), "r"(b[1]));
}

// =====================================================================
// Pass 1 (tf32 tensor): partial[s] = x[rows] @ w over this split's chunk.
// 256 threads = 8 warps. Warp wid owns m-rows [wid*32, wid*32+32) x all
// 32 cols: 2 m-tiles x 4 n-tiles of m16n8k8 -> acc = 32 f32/thread.
// x tile [256][32] f32 stride 36, w tile [32][32] f32 stride 36 (wT not
// needed: mma "col" B IS w's native [k][n]). cp.async double-buffered.
// =====================================================================
__device__ __forceinline__ void p1_load(unsigned sb, int buf, int tile,
                                        const float* __restrict__ X,
                                        const float* __restrict__ W,
                                        int row0, int t) {
    const int k0 = tile * BK;
    const unsigned xbase = sb + (unsigned)buf * P1_BUF;
    const unsigned wbase = xbase + P1_XS_BYTES;

    // x: 256 rows x 16 u64 -> 16 cp8 per thread; lanes 0..15 cover one row (coalesced 128B)
    const int u  = t & 15;             // u64 index within row (cols 2u, 2u+1)
    const int r0 = t >> 4;             // 0..15
    const int gk = k0 + 2 * u;
    const unsigned szx = (gk < VOCAB) ? 8u : 0u;   // sz=0 -> zero-fill
    const float* srcx = (gk < VOCAB) ? (X + (size_t)(row0 + r0) * VOCAB + gk) : X;
#pragma unroll
    for (int i = 0; i < 16; ++i) {
        int row = i * 16 + r0;
        cp8(xbase + (unsigned)(row * XS_STRIDE + 2 * u) * 4u, srcx, szx);
        srcx += (size_t)16 * VOCAB;
    }

    // w: 32 k-rows x 32 j, native layout ws[k][j]; 4 cp4 per thread
    const int j  = t & 31;
    const int kb = t >> 5;             // 0..7
#pragma unroll
    for (int i = 0; i < 4; ++i) {
        int kk = kb + i * 8;
        int g  = k0 + kk;
        unsigned sz = (g < VOCAB) ? 4u : 0u;
        const float* src = (g < VOCAB) ? (W + (size_t)g * DIM + j) : W;
        cp4(wbase + (unsigned)(kk * XS_STRIDE + j) * 4u, src, sz);
    }
}

__global__ __launch_bounds__(P1_THREADS, 2) void pass1_kernel(const float* __restrict__ X,
                                                              const float* __restrict__ W) {
    extern __shared__ char smem[];
    const unsigned sb = smem_u32(smem);

    const int t    = threadIdx.x;
    const int lane = t & 31;
    const int wid  = t >> 5;           // 0..7 -> m-slab
    const int g    = lane >> 2;        // groupID 0..7
    const int tig  = lane & 3;         // threadID_in_group
    const int row0 = blockIdx.x * BM;
    const int s    = blockIdx.y;

    float acc[32];                     // [mt][nt][4]
#pragma unroll
    for (int i = 0; i < 32; ++i) acc[i] = 0.f;

    const int tile0 = s * TPS;
    const int tile1 = (tile0 + TPS < NTILES) ? (tile0 + TPS) : NTILES;
    const int nt_   = tile1 - tile0;

    p1_load(sb, 0, tile0, X, W, row0, t);
    CP_COMMIT();

    const int mrow = wid * 32 + g;     // base row of this thread's a-frags

    for (int i = 0; i < nt_; ++i) {
        if (i + 1 < nt_) p1_load(sb, (i + 1) & 1, tile0 + i + 1, X, W, row0, t);
        CP_COMMIT();
        CP_WAIT1();
        __syncthreads();

        const float* xp = reinterpret_cast<const float*>(smem + (i & 1) * P1_BUF);
        const float* wp = reinterpret_cast<const float*>(smem + (i & 1) * P1_BUF + P1_XS_BYTES);

#pragma unroll
        for (int ks = 0; ks < 4; ++ks) {
            const int kc = ks * 8;
            uint32_t a[2][4], b[4][2];
#pragma unroll
            for (int mt = 0; mt < 2; ++mt) {
                const float* ap = xp + (mrow + mt * 16) * XS_STRIDE + kc + tig;
                a[mt][0] = to_tf32(ap[0]);
                a[mt][1] = to_tf32(ap[8 * XS_STRIDE]);
                a[mt][2] = to_tf32(ap[4]);
                a[mt][3] = to_tf32(ap[8 * XS_STRIDE + 4]);
            }
#pragma unroll
            for (int nt2 = 0; nt2 < 4; ++nt2) {
                const float* bp = wp + (kc + tig) * XS_STRIDE + nt2 * 8 + g;
                b[nt2][0] = to_tf32(bp[0]);
                b[nt2][1] = to_tf32(bp[4 * XS_STRIDE]);
            }
#pragma unroll
            for (int mt = 0; mt < 2; ++mt)
#pragma unroll
                for (int nt2 = 0; nt2 < 4; ++nt2)
                    mma_tf32(&acc[(mt * 4 + nt2) * 4], a[mt], b[nt2]);
        }
        __syncthreads();
    }

    // epilogue: D[g][2tig],[2tig+1] and rows +8 per (mt, nt)
#pragma unroll
    for (int mt = 0; mt < 2; ++mt) {
#pragma unroll
        for (int nt2 = 0; nt2 < 4; ++nt2) {
            const float* d = &acc[(mt * 4 + nt2) * 4];
            int r = row0 + mrow + mt * 16;
            int c = nt2 * 8 + 2 * tig;
            float2 lo = make_float2(d[0], d[1]);
            float2 hi = make_float2(d[2], d[3]);
            *reinterpret_cast<float2*>(&g_partial[((size_t)s * BATCH + r) * DIM + c]) = lo;
            *reinterpret_cast<float2*>(&g_partial[((size_t)s * BATCH + r + 8) * DIM + c]) = hi;
        }
    }
}

// =====================================================================
// Reduce partials + bias + sigmoid -> g_h
// =====================================================================
__global__ void reduce_act_kernel(const float* __restrict__ b) {
    int idx = blockIdx.x * blockDim.x + threadIdx.x;
    if (idx >= BATCH * DIM) return;
    float sum = b[idx & (DIM - 1)];
#pragma unroll
    for (int s = 0; s < NSPLIT; ++s)
        sum += g_partial[(size_t)s * BATCH * DIM + idx];
    g_h[idx] = sigt(sum);
}

// =====================================================================
// Pass 2: y = sigmoid(h @ w^T)   [round-5 passing version, unchanged]
// =====================================================================
__device__ __forceinline__ void p2_load(unsigned hbase, int buf, int ib, int t) {
    const unsigned dst0 = hbase + (unsigned)buf * (P2_ROWS * DIM * 4);
#pragma unroll
    for (int i = 0; i < 2; ++i) {
        int e   = i * P2_THREADS + t;
        int row = e >> 3;
        int q   = e & 7;
        cp16(dst0 + (unsigned)(row * DIM + q * 4) * 4u,
             &g_h[(size_t)(ib + row) * DIM + q * 4]);
    }
}

__global__ __launch_bounds__(P2_THREADS, 2) void pass2_kernel(const float* __restrict__ W,
                                                              float* __restrict__ Y) {
    __shared__ float hs[2][P2_ROWS * DIM];  // 16 KB
    const unsigned hbase = smem_u32(&hs[0][0]);

    const int t   = threadIdx.x;
    const int jb  = blockIdx.x * P2_JSPAN;
    const int ib0 = blockIdx.y * (P2_ROWS * P2_CHUNKS);

    p2_load(hbase, 0, ib0, t);
    CP_COMMIT();

    const int j = jb + 2 * t;                 // even; j valid => j+1 valid
    const bool valid = (j < VOCAB);

    u64 wa[16], wb[16];
    if (valid) {
        const u64* pa = reinterpret_cast<const u64*>(W + (size_t)j * DIM);
        const u64* pb = pa + 16;              // row j+1
#pragma unroll
        for (int p = 0; p < 16; ++p) { wa[p] = pa[p]; wb[p] = pb[p]; }
    }

    for (int c = 0; c < P2_CHUNKS; ++c) {
        if (c + 1 < P2_CHUNKS) p2_load(hbase, (c + 1) & 1, ib0 + (c + 1) * P2_ROWS, t);
        CP_COMMIT();
        CP_WAIT1();
        __syncthreads();

        if (valid) {
            const float* hb = &hs[c & 1][0];
            const int ib = ib0 + c * P2_ROWS;
#pragma unroll 2
            for (int r = 0; r < P2_ROWS; ++r) {
                u64 aa = 0ULL, ab = 0ULL;
#pragma unroll
                for (int p = 0; p < 16; ++p) {
                    u64 h2 = *reinterpret_cast<const u64*>(&hb[r * DIM + 2 * p]);
                    aa = fma2(h2, wa[p], aa);
                    ab = fma2(h2, wb[p], ab);
                }
                float2 o;
                o.x = sigt(lanesum(aa));
                o.y = sigt(lanesum(ab));
                *reinterpret_cast<float2*>(&Y[(size_t)(ib + r) * VOCAB + j]) = o;
            }
        }
        __syncthreads();
    }
}

// =====================================================================
extern "C" void kernel_launch(void* const* d_in, const int* in_sizes, int n_in,
                              void* d_out, int out_size) {
    const float* x = (const float*)d_in[0];  // [4096, 81616]
    const float* w = (const float*)d_in[1];  // [81616, 32]
    const float* b = (const float*)d_in[2];  // [32]
    float* y = (float*)d_out;                // [4096, 81616]

    cudaFuncSetAttribute(pass1_kernel, cudaFuncAttributeMaxDynamicSharedMemorySize, P1_SMEM);

    dim3 g1(ROWBLOCKS, NSPLIT);
    pass1_kernel<<<g1, P1_THREADS, P1_SMEM>>>(x, w);

    reduce_act_kernel<<<(BATCH * DIM + 255) / 256, 256>>>(b);

    dim3 g2((VOCAB + P2_JSPAN - 1) / P2_JSPAN, BATCH / (P2_ROWS * P2_CHUNKS));
    pass2_kernel<<<g2, P2_THREADS>>>(w, y);
}

// round 7
// speedup vs baseline: 3.4365x; 1.4971x over previous
#include <cuda_runtime.h>
#include <cstdint>

#define VOCAB 81616
#define DIM 32
#define BATCH 4096

typedef unsigned long long u64;

// ---------------- pass 1 config ----------------
#define BM 256
#define BK 32
#define NSPLIT 18
#define NTILES ((VOCAB + BK - 1) / BK)        // 2551
#define TPS ((NTILES + NSPLIT - 1) / NSPLIT)  // 142
#define ROWBLOCKS (BATCH / BM)                // 16
#define P1_THREADS 256

#define XS_STRIDE 36                          // 144B rows: 16B-aligned, bank=4r+c
#define P1_XS_BYTES (BM * XS_STRIDE * 4)      // 36864
#define P1_WS_BYTES (BK * XS_STRIDE * 4)      // 4608
#define P1_BUF (P1_XS_BYTES + P1_WS_BYTES)    // 41472
#define P1_SMEM (2 * P1_BUF)                  // 82944

// ---------------- pass 2 config ----------------
#define P2_THREADS 256
#define P2_MROWS 64                           // CTA rows per chunk (4 m-warps x 16)
#define P2_COLS 128                           // CTA cols (2 n-warps x 64)
#define P2_YSPLIT 4
#define P2_CHUNKS ((BATCH / P2_YSPLIT) / P2_MROWS)  // 16
#define HS_STRIDE 36

// Scratch (no cudaMalloc allowed — device globals)
__device__ __align__(16) float g_partial[NSPLIT * BATCH * DIM];  // 9.4 MB
__device__ __align__(16) float g_h[BATCH * DIM];                 // 512 KB (tf32-rounded)

// ---------------- helpers ----------------
// sigmoid(x) = 0.5*tanh(0.5x) + 0.5
__device__ __forceinline__ float sigt(float x) {
    float t;
    asm("tanh.approx.f32 %0, %1;" : "=f"(t) : "f"(x * 0.5f));
    return fmaf(0.5f, t, 0.5f);
}

__device__ __forceinline__ unsigned smem_u32(const void* p) {
    unsigned a;
    asm("{ .reg .u64 t; cvta.to.shared.u64 t, %1; cvt.u32.u64 %0, t; }" : "=r"(a) : "l"(p));
    return a;
}

__device__ __forceinline__ void cp8(unsigned dst, const void* src, unsigned sz) {
    asm volatile("cp.async.ca.shared.global [%0], [%1], 8, %2;" :: "r"(dst), "l"(src), "r"(sz));
}
__device__ __forceinline__ void cp4(unsigned dst, const void* src, unsigned sz) {
    asm volatile("cp.async.ca.shared.global [%0], [%1], 4, %2;" :: "r"(dst), "l"(src), "r"(sz));
}
__device__ __forceinline__ void cp16(unsigned dst, const void* src) {
    asm volatile("cp.async.ca.shared.global [%0], [%1], 16;" :: "r"(dst), "l"(src));
}
#define CP_COMMIT() asm volatile("cp.async.commit_group;")
#define CP_WAIT1()  asm volatile("cp.async.wait_group 1;")

// round-to-nearest tf32 (unbiased)
__device__ __forceinline__ uint32_t to_tf32(float f) {
    uint32_t r;
    asm("cvt.rna.tf32.f32 %0, %1;" : "=r"(r) : "f"(f));
    return r;
}

__device__ __forceinline__ void mma_tf32(float* d, const uint32_t* a, const uint32_t* b) {
    asm("mma.sync.aligned.m16n8k8.row.col.f32.tf32.tf32.f32 "
        "{%0,%1,%2,%3}, {%4,%5,%6,%7}, {%8,%9}, {%0,%1,%2,%3};"
        : "+f"(d[0]), "+f"(d[1]), "+f"(d[2]), "+f"(d[3])
        : "r"(a[0]), "r"(a[1]), "r"(a[2]), "r"(a[3]), "r"(b[0]), "r"(b[1]));
}

// =====================================================================
// Pass 1 (tf32 tensor) — unchanged from round-6 passing version.
// =====================================================================
__device__ __forceinline__ void p1_load(unsigned sb, int buf, int tile,
                                        const float* __restrict__ X,
                                        const float* __restrict__ W,
                                        int row0, int t) {
    const int k0 = tile * BK;
    const unsigned xbase = sb + (unsigned)buf * P1_BUF;
    const unsigned wbase = xbase + P1_XS_BYTES;

    const int u  = t & 15;
    const int r0 = t >> 4;
    const int gk = k0 + 2 * u;
    const unsigned szx = (gk < VOCAB) ? 8u : 0u;
    const float* srcx = (gk < VOCAB) ? (X + (size_t)(row0 + r0) * VOCAB + gk) : X;
#pragma unroll
    for (int i = 0; i < 16; ++i) {
        int row = i * 16 + r0;
        cp8(xbase + (unsigned)(row * XS_STRIDE + 2 * u) * 4u, srcx, szx);
        srcx += (size_t)16 * VOCAB;
    }

    const int j  = t & 31;
    const int kb = t >> 5;
#pragma unroll
    for (int i = 0; i < 4; ++i) {
        int kk = kb + i * 8;
        int g  = k0 + kk;
        unsigned sz = (g < VOCAB) ? 4u : 0u;
        const float* src = (g < VOCAB) ? (W + (size_t)g * DIM + j) : W;
        cp4(wbase + (unsigned)(kk * XS_STRIDE + j) * 4u, src, sz);
    }
}

__global__ __launch_bounds__(P1_THREADS, 2) void pass1_kernel(const float* __restrict__ X,
                                                              const float* __restrict__ W) {
    extern __shared__ char smem[];
    const unsigned sb = smem_u32(smem);

    const int t    = threadIdx.x;
    const int lane = t & 31;
    const int wid  = t >> 5;
    const int g    = lane >> 2;
    const int tig  = lane & 3;
    const int row0 = blockIdx.x * BM;
    const int s    = blockIdx.y;

    float acc[32];
#pragma unroll
    for (int i = 0; i < 32; ++i) acc[i] = 0.f;

    const int tile0 = s * TPS;
    const int tile1 = (tile0 + TPS < NTILES) ? (tile0 + TPS) : NTILES;
    const int nt_   = tile1 - tile0;

    p1_load(sb, 0, tile0, X, W, row0, t);
    CP_COMMIT();

    const int mrow = wid * 32 + g;

    for (int i = 0; i < nt_; ++i) {
        if (i + 1 < nt_) p1_load(sb, (i + 1) & 1, tile0 + i + 1, X, W, row0, t);
        CP_COMMIT();
        CP_WAIT1();
        __syncthreads();

        const float* xp = reinterpret_cast<const float*>(smem + (i & 1) * P1_BUF);
        const float* wp = reinterpret_cast<const float*>(smem + (i & 1) * P1_BUF + P1_XS_BYTES);

#pragma unroll
        for (int ks = 0; ks < 4; ++ks) {
            const int kc = ks * 8;
            uint32_t a[2][4], b[4][2];
#pragma unroll
            for (int mt = 0; mt < 2; ++mt) {
                const float* ap = xp + (mrow + mt * 16) * XS_STRIDE + kc + tig;
                a[mt][0] = to_tf32(ap[0]);
                a[mt][1] = to_tf32(ap[8 * XS_STRIDE]);
                a[mt][2] = to_tf32(ap[4]);
                a[mt][3] = to_tf32(ap[8 * XS_STRIDE + 4]);
            }
#pragma unroll
            for (int nt2 = 0; nt2 < 4; ++nt2) {
                const float* bp = wp + (kc + tig) * XS_STRIDE + nt2 * 8 + g;
                b[nt2][0] = to_tf32(bp[0]);
                b[nt2][1] = to_tf32(bp[4 * XS_STRIDE]);
            }
#pragma unroll
            for (int mt = 0; mt < 2; ++mt)
#pragma unroll
                for (int nt2 = 0; nt2 < 4; ++nt2)
                    mma_tf32(&acc[(mt * 4 + nt2) * 4], a[mt], b[nt2]);
        }
        __syncthreads();
    }

#pragma unroll
    for (int mt = 0; mt < 2; ++mt) {
#pragma unroll
        for (int nt2 = 0; nt2 < 4; ++nt2) {
            const float* d = &acc[(mt * 4 + nt2) * 4];
            int r = row0 + mrow + mt * 16;
            int c = nt2 * 8 + 2 * tig;
            float2 lo = make_float2(d[0], d[1]);
            float2 hi = make_float2(d[2], d[3]);
            *reinterpret_cast<float2*>(&g_partial[((size_t)s * BATCH + r) * DIM + c]) = lo;
            *reinterpret_cast<float2*>(&g_partial[((size_t)s * BATCH + r + 8) * DIM + c]) = hi;
        }
    }
}

// =====================================================================
// Reduce partials + bias + sigmoid -> g_h, PRE-ROUNDED to tf32 so pass2
// consumes A-fragments with plain LDS.32 (no cvt in the hot loop).
// =====================================================================
__global__ void reduce_act_kernel(const float* __restrict__ b) {
    int idx = blockIdx.x * blockDim.x + threadIdx.x;
    if (idx >= BATCH * DIM) return;
    float sum = b[idx & (DIM - 1)];
#pragma unroll
    for (int s = 0; s < NSPLIT; ++s)
        sum += g_partial[(size_t)s * BATCH * DIM + idx];
    g_h[idx] = __uint_as_float(to_tf32(sigt(sum)));
}

// =====================================================================
// Pass 2 (tf32 tensor): y = sigmoid(h @ w^T).
// CTA: 256 thr = 8 warps (4 m x 2 n) = 64 rows x 128 cols per chunk.
// Warp: 16 rows x 64 cols = 8 n-tiles of m16n8k8 (4 k-steps), acc=32.
// B-fragments (w) register-resident: w's [j][k] row-major IS mma col-major
// B — loaded once per CTA (64 regs). h chunks double-buffered cp.async,
// stride 36 -> A-frag LDS.32 bank = 4g+tig (+4), conflict-free.
// Output stores: float2 at 32B-sector-aligned addrs, full sectors.
// VOCAB % 8 == 0 -> n-tiles at the grid tail are all-valid or all-invalid.
// =====================================================================
__device__ __forceinline__ void p2_load(unsigned hbase, int buf, int ib, int t) {
    const unsigned dst0 = hbase + (unsigned)buf * (P2_MROWS * HS_STRIDE * 4);
#pragma unroll
    for (int i = 0; i < 2; ++i) {
        int e   = i * P2_THREADS + t;
        int row = e >> 3;
        int q   = e & 7;
        cp16(dst0 + (unsigned)(row * HS_STRIDE + q * 4) * 4u,
             &g_h[(size_t)(ib + row) * DIM + q * 4]);
    }
}

__global__ __launch_bounds__(P2_THREADS, 2) void pass2_kernel(const float* __restrict__ W,
                                                              float* __restrict__ Y) {
    __shared__ float hs[2][P2_MROWS * HS_STRIDE];  // 18.4 KB
    const unsigned hbase = smem_u32(&hs[0][0]);

    const int t    = threadIdx.x;
    const int lane = t & 31;
    const int wid  = t >> 5;
    const int wm   = wid & 3;            // m-warp 0..3
    const int wn   = wid >> 2;           // n-warp 0..1
    const int g    = lane >> 2;
    const int tig  = lane & 3;
    const int c0   = blockIdx.x * P2_COLS + wn * 64;   // warp col base
    const int ib0  = blockIdx.y * (BATCH / P2_YSPLIT);

    // ---- B fragments: w rows register-resident, tf32, loaded once ----
    uint32_t bw[8][4][2];
#pragma unroll
    for (int nt = 0; nt < 8; ++nt) {
        int j = c0 + nt * 8 + g;
        bool v = (j < VOCAB);
        const float* wr = W + (size_t)(v ? j : 0) * DIM;
#pragma unroll
        for (int ks = 0; ks < 4; ++ks) {
            bw[nt][ks][0] = to_tf32(v ? wr[ks * 8 + tig]     : 0.f);
            bw[nt][ks][1] = to_tf32(v ? wr[ks * 8 + tig + 4] : 0.f);
        }
    }

    p2_load(hbase, 0, ib0, t);
    CP_COMMIT();

    for (int c = 0; c < P2_CHUNKS; ++c) {
        if (c + 1 < P2_CHUNKS) p2_load(hbase, (c + 1) & 1, ib0 + (c + 1) * P2_MROWS, t);
        CP_COMMIT();
        CP_WAIT1();
        __syncthreads();

        const float* hb = hs[c & 1];
        float acc[8][4];
#pragma unroll
        for (int nt = 0; nt < 8; ++nt)
#pragma unroll
            for (int i = 0; i < 4; ++i) acc[nt][i] = 0.f;

#pragma unroll
        for (int ks = 0; ks < 4; ++ks) {
            uint32_t a[4];
            const float* ap = hb + (wm * 16 + g) * HS_STRIDE + ks * 8 + tig;
            a[0] = __float_as_uint(ap[0]);
            a[1] = __float_as_uint(ap[8 * HS_STRIDE]);
            a[2] = __float_as_uint(ap[4]);
            a[3] = __float_as_uint(ap[8 * HS_STRIDE + 4]);
#pragma unroll
            for (int nt = 0; nt < 8; ++nt)
                mma_tf32(acc[nt], a, bw[nt][ks]);
        }

        // epilogue: sigmoid + store (n-tile validity is uniform: 8 | VOCAB)
        const size_t r0 = (size_t)(ib0 + c * P2_MROWS + wm * 16 + g);
#pragma unroll
        for (int nt = 0; nt < 8; ++nt) {
            int colb = c0 + nt * 8;
            if (colb < VOCAB) {
                int col = colb + 2 * tig;
                float2 lo = make_float2(sigt(acc[nt][0]), sigt(acc[nt][1]));
                float2 hi = make_float2(sigt(acc[nt][2]), sigt(acc[nt][3]));
                *reinterpret_cast<float2*>(&Y[r0 * VOCAB + col])       = lo;
                *reinterpret_cast<float2*>(&Y[(r0 + 8) * VOCAB + col]) = hi;
            }
        }
        __syncthreads();
    }
}

// =====================================================================
extern "C" void kernel_launch(void* const* d_in, const int* in_sizes, int n_in,
                              void* d_out, int out_size) {
    const float* x = (const float*)d_in[0];  // [4096, 81616]
    const float* w = (const float*)d_in[1];  // [81616, 32]
    const float* b = (const float*)d_in[2];  // [32]
    float* y = (float*)d_out;                // [4096, 81616]

    cudaFuncSetAttribute(pass1_kernel, cudaFuncAttributeMaxDynamicSharedMemorySize, P1_SMEM);

    dim3 g1(ROWBLOCKS, NSPLIT);
    pass1_kernel<<<g1, P1_THREADS, P1_SMEM>>>(x, w);

    reduce_act_kernel<<<(BATCH * DIM + 255) / 256, 256>>>(b);

    dim3 g2((VOCAB + P2_COLS - 1) / P2_COLS, P2_YSPLIT);
    pass2_kernel<<<g2, P2_THREADS>>>(w, y);
}